// round 3
// baseline (speedup 1.0000x reference)
#include <cuda_runtime.h>
#include <math.h>

#define NN 50000
#define EE 800000
#define HH 128
#define EDIM 32
#define GG 64
#define AA 16
#define BN_EPS 1e-5f
#define NB 196                      // ceil(NN/256)
#define FULLM 0xffffffffu

// ---------------- scratch (static device globals; no allocation) ----------------
__device__ float g_y[(size_t)NN * HH];
__device__ float g_u[(size_t)NN * HH];
__device__ float g_h[(size_t)NN * HH];
__device__ float g_sum[HH];
__device__ float g_sumsq[HH];
__device__ float g_scale[HH];
__device__ float g_shift[HH];
__device__ float g_pooled[GG * HH];
__device__ int   g_idx64;
// sort scratch
__device__ int g_cnt[NN];
__device__ int g_cur[NN];
__device__ int g_bsum[256];
__device__ int g_boff[256];
__device__ int g_eid[EE];
__device__ int g_ssrc[EE];
__device__ int g_sdst[EE];

// ---------------- int32/int64 index handling ----------------
__device__ __forceinline__ long long read_idx(const void* p, long long i, bool i64) {
    if (i64) return ((const long long*)p)[i];
    return (long long)((const int*)p)[i];
}

__global__ void detect_kernel(const unsigned int* __restrict__ w) {
    __shared__ int f;
    if (threadIdx.x == 0) f = 0;
    __syncthreads();
    int local = 0;
    for (int i = threadIdx.x * 2 + 1; i < 8192; i += 512)
        if (w[i]) local = 1;
    if (local) atomicOr(&f, 1);
    __syncthreads();
    if (threadIdx.x == 0) g_idx64 = f ? 0 : 1;
}

// ---------------- counting sort by dst ----------------
__global__ void zero_cnt_kernel() {
    int i = blockIdx.x * blockDim.x + threadIdx.x;
    if (i < NN) g_cnt[i] = 0;
}

__global__ void hist_kernel(const void* __restrict__ eiv) {
    bool i64 = (g_idx64 != 0);
    int e = blockIdx.x * blockDim.x + threadIdx.x;
    if (e < EE) {
        int d = (int)read_idx(eiv, (long long)EE + e, i64);
        atomicAdd(&g_cnt[d], 1);
    }
}

__global__ void bsum_kernel() {
    __shared__ int s[256];
    int t = threadIdx.x, i = blockIdx.x * 256 + t;
    s[t] = (i < NN) ? g_cnt[i] : 0;
    __syncthreads();
    for (int d = 128; d > 0; d >>= 1) {
        if (t < d) s[t] += s[t + d];
        __syncthreads();
    }
    if (t == 0) g_bsum[blockIdx.x] = s[0];
}

__global__ void scan_bsum_kernel() {
    __shared__ int s[256];
    int t = threadIdx.x;
    int v = (t < NB) ? g_bsum[t] : 0;
    s[t] = v;
    __syncthreads();
    for (int d = 1; d < 256; d <<= 1) {
        int u = (t >= d) ? s[t - d] : 0;
        __syncthreads();
        s[t] += u;
        __syncthreads();
    }
    if (t < NB) g_boff[t] = s[t] - v;   // exclusive
}

__global__ void offs_kernel() {
    __shared__ int s[256];
    int t = threadIdx.x, i = blockIdx.x * 256 + t;
    int v = (i < NN) ? g_cnt[i] : 0;
    s[t] = v;
    __syncthreads();
    for (int d = 1; d < 256; d <<= 1) {
        int u = (t >= d) ? s[t - d] : 0;
        __syncthreads();
        s[t] += u;
        __syncthreads();
    }
    if (i < NN) g_cur[i] = s[t] - v + g_boff[blockIdx.x];
}

__global__ void scatter_kernel(const void* __restrict__ eiv) {
    bool i64 = (g_idx64 != 0);
    int e = blockIdx.x * blockDim.x + threadIdx.x;
    if (e < EE) {
        int sv = (int)read_idx(eiv, e, i64);
        int d  = (int)read_idx(eiv, (long long)EE + e, i64);
        int p = atomicAdd(&g_cur[d], 1);
        g_eid[p] = e;
        g_ssrc[p] = sv;
        g_sdst[p] = d;
    }
}

// ---------------- tf32 helpers ----------------
__device__ __forceinline__ unsigned tf32_of(float f) {
    unsigned u;
    asm("cvt.rna.tf32.f32 %0, %1;" : "=r"(u) : "f"(f));
    return u;
}
__device__ __forceinline__ void split_tf32(float f, unsigned& hi, unsigned& lo) {
    hi = tf32_of(f);
    lo = tf32_of(f - __uint_as_float(hi));
}
__device__ __forceinline__ void mma_tf32(float& c0, float& c1, float& c2, float& c3,
                                         unsigned a0, unsigned a1, unsigned a2, unsigned a3,
                                         unsigned b0, unsigned b1) {
    asm volatile("mma.sync.aligned.m16n8k8.row.col.f32.tf32.tf32.f32 "
                 "{%0,%1,%2,%3}, {%4,%5,%6,%7}, {%8,%9}, {%0,%1,%2,%3};"
                 : "+f"(c0), "+f"(c1), "+f"(c2), "+f"(c3)
                 : "r"(a0), "r"(a1), "r"(a2), "r"(a3), "r"(b0), "r"(b1));
}

// ---------------- y = src (copy), zero BN stats ----------------
__global__ void copy_init_kernel(const float4* __restrict__ src, int n4) {
    if (blockIdx.x == 0 && threadIdx.x < HH) {
        g_sum[threadIdx.x] = 0.f;
        g_sumsq[threadIdx.x] = 0.f;
    }
    int i = blockIdx.x * blockDim.x + threadIdx.x;
    if (i < n4) ((float4*)g_y)[i] = src[i];
}

// ---------------- edge kernel: sorted edges, mma elin, segmented-scan epilogue ----------------
#define NTILES 50000     // EE/16
#define WTILES 8
__global__ void __launch_bounds__(256) edge_sorted_kernel(
    const float* __restrict__ xin_ext, int use_h,
    const float* __restrict__ ea,
    const float* __restrict__ We,   // [128][32] row-major
    const float* __restrict__ be)
{
    __shared__ float4 bfrag[16 * 4 * 32];
    __shared__ float be_s[HH];

    const int tid = threadIdx.x;
    for (int idx = tid; idx < 2048; idx += 256) {
        int nt = idx >> 7, kk = (idx >> 5) & 3, ln = idx & 31;
        int g2 = ln >> 2, t2 = ln & 3;
        int c = nt * 8 + g2;
        float w0 = We[c * EDIM + 8 * t2 + kk];
        float w1 = We[c * EDIM + 8 * t2 + 4 + kk];
        unsigned h0, l0, h1, l1;
        split_tf32(w0, h0, l0);
        split_tf32(w1, h1, l1);
        bfrag[idx] = make_float4(__uint_as_float(h0), __uint_as_float(h1),
                                 __uint_as_float(l0), __uint_as_float(l1));
    }
    if (tid < HH) be_s[tid] = be[tid];
    __syncthreads();

    const float* __restrict__ xin = use_h ? g_h : xin_ext;
    const int lane = tid & 31, warp = tid >> 5;
    const int g = lane >> 2, t = lane & 3;
    const bool even = ((t & 1) == 0);
    const int cboff = (t & 2) ? 4 : 0;
    const int lgrp = lane & 2;                 // lane offset of my cboff group
    const int j = (g << 1) | (t & 1);          // logical sorted-edge slot 0..15

    for (int it = 0; it < WTILES; it++) {
        int tile = (blockIdx.x * 8 + warp) * WTILES + it;
        if (tile >= NTILES) break;
        int p0 = tile * 16;

        int eidv = 0, srcv = 0, dstv = 0;
        if (lane < 16) {
            eidv = g_eid[p0 + lane];
            srcv = g_ssrc[p0 + lane];
            dstv = g_sdst[p0 + lane];
        }
        int prevd = __shfl_up_sync(FULLM, dstv, 1);
        bool bflag = (lane == 0) || (dstv != prevd);
        unsigned mask16 = __ballot_sync(FULLM, (lane < 16) && bflag) & 0xFFFFu;

        int my_src = __shfl_sync(FULLM, srcv, j);
        int my_dst = __shfl_sync(FULLM, dstv, j);
        int head = 31 - __clz(mask16 & ((2u << j) - 1u));
        bool is_tail = (j == 15) || ((mask16 >> (j + 1)) & 1u);

        const float* srcp = xin + (size_t)my_src * HH + cboff;
        float*       dstp = g_y + (size_t)my_dst * HH + cboff;

        // mma row g <- sorted slot 2g ; row g+8 <- slot 2g+1
        int ea0 = __shfl_sync(FULLM, eidv, 2 * g);
        int ea1 = __shfl_sync(FULLM, eidv, 2 * g + 1);
        const float* ar0 = ea + (size_t)ea0 * EDIM + 8 * t;
        const float* ar1 = ea + (size_t)ea1 * EDIM + 8 * t;
        float4 u0 = *(const float4*)ar0;
        float4 u1 = *(const float4*)(ar0 + 4);
        float4 v0 = *(const float4*)ar1;
        float4 v1 = *(const float4*)(ar1 + 4);
        float ua0[4] = {u0.x, u0.y, u0.z, u0.w};
        float ua1[4] = {u1.x, u1.y, u1.z, u1.w};
        float va0[4] = {v0.x, v0.y, v0.z, v0.w};
        float va1[4] = {v1.x, v1.y, v1.z, v1.w};

        unsigned ahi[4][4], alo[4][4];
#pragma unroll
        for (int kk = 0; kk < 4; kk++) {
            split_tf32(ua0[kk], ahi[kk][0], alo[kk][0]);
            split_tf32(va0[kk], ahi[kk][1], alo[kk][1]);
            split_tf32(ua1[kk], ahi[kk][2], alo[kk][2]);
            split_tf32(va1[kk], ahi[kk][3], alo[kk][3]);
        }

#pragma unroll 2
        for (int nt = 0; nt < 16; nt++) {
            float2 b2 = *(const float2*)(be_s + nt * 8 + 2 * t);
            float c0 = b2.x, c1 = b2.y, c2 = b2.x, c3 = b2.y;
#pragma unroll
            for (int kk = 0; kk < 4; kk++) {
                float4 bf = bfrag[(nt * 4 + kk) * 32 + lane];
                unsigned bh0 = __float_as_uint(bf.x), bh1 = __float_as_uint(bf.y);
                unsigned bl0 = __float_as_uint(bf.z), bl1 = __float_as_uint(bf.w);
                mma_tf32(c0, c1, c2, c3, ahi[kk][0], ahi[kk][1], ahi[kk][2], ahi[kk][3], bh0, bh1);
                mma_tf32(c0, c1, c2, c3, alo[kk][0], alo[kk][1], alo[kk][2], alo[kk][3], bh0, bh1);
                mma_tf32(c0, c1, c2, c3, ahi[kk][0], ahi[kk][1], ahi[kk][2], ahi[kk][3], bl0, bl1);
            }
            // pair exchange -> float4 of edge j at cols nt*8+cboff
            float s0 = even ? c2 : c0;
            float s1 = even ? c3 : c1;
            float r0 = __shfl_xor_sync(FULLM, s0, 1);
            float r1 = __shfl_xor_sync(FULLM, s1, 1);
            float4 acc;
            if (even) { acc = make_float4(c0, c1, r0, r1); }
            else      { acc = make_float4(r0, r1, c2, c3); }

            float4 xv = *(const float4*)(srcp + nt * 8);
            acc.x = fmaxf(acc.x + xv.x, 0.f);
            acc.y = fmaxf(acc.y + xv.y, 0.f);
            acc.z = fmaxf(acc.z + xv.z, 0.f);
            acc.w = fmaxf(acc.w + xv.w, 0.f);

            // segmented inclusive scan over logical j (4 rounds)
#pragma unroll
            for (int d = 1; d < 16; d <<= 1) {
                int sj = j - d;
                int sjc = sj < 0 ? 0 : sj;
                int sl = ((sjc >> 1) << 2) | (sjc & 1) | lgrp;
                float vx = __shfl_sync(FULLM, acc.x, sl);
                float vy = __shfl_sync(FULLM, acc.y, sl);
                float vz = __shfl_sync(FULLM, acc.z, sl);
                float vw = __shfl_sync(FULLM, acc.w, sl);
                if (sj >= head) {
                    acc.x += vx; acc.y += vy; acc.z += vz; acc.w += vw;
                }
            }
            if (is_tail) {
                asm volatile("red.global.add.v4.f32 [%0], {%1,%2,%3,%4};"
                             :: "l"(dstp + nt * 8),
                                "f"(acc.x), "f"(acc.y), "f"(acc.z), "f"(acc.w) : "memory");
            }
        }
    }
}

// ---------------- node GEMM via tensor cores: u = g_y @ W.T + b ----------------
// 512 threads, 16 warps. Warp: 16 rows x 64 cols (colhalf). Block: 128 rows x 128 cols.
__global__ void __launch_bounds__(512) node_gemm_mma_kernel(
    const float* __restrict__ W,
    const float* __restrict__ b)
{
    __shared__ float4 bfrag[16 * 4 * 32];
    __shared__ float b_s[HH];

    const int tid = threadIdx.x;
    const int lane = tid & 31, warp = tid >> 5;
    const int g = lane >> 2, t = lane & 3;
    const int colhalf = warp >> 3;           // 0/1
    const int rw = warp & 7;                 // row-warp 0..7
    const int nt0 = colhalf * 8;
    const int rowbase = blockIdx.x * 128 + rw * 16;
    const bool active = (rowbase < NN);
    const bool even = ((t & 1) == 0);
    const int cboff = (t & 2) ? 4 : 0;

    if (tid < HH) b_s[tid] = b[tid];

    float C[8][4];
#pragma unroll
    for (int nt = 0; nt < 8; nt++)
#pragma unroll
        for (int q = 0; q < 4; q++) C[nt][q] = 0.f;

    for (int kb = 0; kb < 4; kb++) {
        __syncthreads();
        for (int idx = tid; idx < 2048; idx += 512) {
            int nt = idx >> 7, kk = (idx >> 5) & 3, ln = idx & 31;
            int g2 = ln >> 2, t2 = ln & 3;
            int c = nt * 8 + g2;
            int k0 = kb * 32 + 8 * t2 + kk;
            float w0 = W[c * HH + k0];
            float w1 = W[c * HH + k0 + 4];
            unsigned h0, l0, h1, l1;
            split_tf32(w0, h0, l0);
            split_tf32(w1, h1, l1);
            bfrag[idx] = make_float4(__uint_as_float(h0), __uint_as_float(h1),
                                     __uint_as_float(l0), __uint_as_float(l1));
        }
        __syncthreads();

        if (active) {
            const float* ar0 = g_y + (size_t)(rowbase + g) * HH + kb * 32 + 8 * t;
            const float* ar1 = g_y + (size_t)(rowbase + g + 8) * HH + kb * 32 + 8 * t;
            float4 u0 = *(const float4*)ar0;
            float4 u1 = *(const float4*)(ar0 + 4);
            float4 v0 = *(const float4*)ar1;
            float4 v1 = *(const float4*)(ar1 + 4);
            float ua0[4] = {u0.x, u0.y, u0.z, u0.w};
            float ua1[4] = {u1.x, u1.y, u1.z, u1.w};
            float va0[4] = {v0.x, v0.y, v0.z, v0.w};
            float va1[4] = {v1.x, v1.y, v1.z, v1.w};

            unsigned ahi[4][4], alo[4][4];
#pragma unroll
            for (int kk = 0; kk < 4; kk++) {
                split_tf32(ua0[kk], ahi[kk][0], alo[kk][0]);
                split_tf32(va0[kk], ahi[kk][1], alo[kk][1]);
                split_tf32(ua1[kk], ahi[kk][2], alo[kk][2]);
                split_tf32(va1[kk], ahi[kk][3], alo[kk][3]);
            }
#pragma unroll
            for (int ntl = 0; ntl < 8; ntl++) {
                int nt = nt0 + ntl;
#pragma unroll
                for (int kk = 0; kk < 4; kk++) {
                    float4 bf = bfrag[(nt * 4 + kk) * 32 + lane];
                    unsigned bh0 = __float_as_uint(bf.x), bh1 = __float_as_uint(bf.y);
                    unsigned bl0 = __float_as_uint(bf.z), bl1 = __float_as_uint(bf.w);
                    mma_tf32(C[ntl][0], C[ntl][1], C[ntl][2], C[ntl][3],
                             ahi[kk][0], ahi[kk][1], ahi[kk][2], ahi[kk][3], bh0, bh1);
                    mma_tf32(C[ntl][0], C[ntl][1], C[ntl][2], C[ntl][3],
                             alo[kk][0], alo[kk][1], alo[kk][2], alo[kk][3], bh0, bh1);
                    mma_tf32(C[ntl][0], C[ntl][1], C[ntl][2], C[ntl][3],
                             ahi[kk][0], ahi[kk][1], ahi[kk][2], ahi[kk][3], bl0, bl1);
                }
            }
        }
    }

    if (active) {
        const int orow = rowbase + (even ? g : g + 8);
        float* outp = g_u + (size_t)orow * HH + cboff;
#pragma unroll
        for (int ntl = 0; ntl < 8; ntl++) {
            int nt = nt0 + ntl;
            float c0 = C[ntl][0] + b_s[nt * 8 + 2 * t];
            float c1 = C[ntl][1] + b_s[nt * 8 + 2 * t + 1];
            float c2 = C[ntl][2] + b_s[nt * 8 + 2 * t];
            float c3 = C[ntl][3] + b_s[nt * 8 + 2 * t + 1];
            float s0 = even ? c2 : c0;
            float s1 = even ? c3 : c1;
            float r0 = __shfl_xor_sync(FULLM, s0, 1);
            float r1 = __shfl_xor_sync(FULLM, s1, 1);
            float4 o;
            if (even) { o = make_float4(c0, c1, r0, r1); }
            else      { o = make_float4(r0, r1, c2, c3); }
            *(float4*)(outp + nt * 8) = o;
        }
    }
}

// ---------------- per-channel BN stats ----------------
__global__ void colreduce_kernel() {
    const int c = threadIdx.x;
    const int r0 = blockIdx.x * 256;
    const int r1 = min(r0 + 256, NN);
    float s = 0.f, s2 = 0.f;
    for (int r = r0; r < r1; r++) {
        float v = g_u[(size_t)r * HH + c];
        s += v; s2 += v * v;
    }
    atomicAdd(&g_sum[c], s);
    atomicAdd(&g_sumsq[c], s2);
}

__global__ void stats_kernel(const float* __restrict__ gamma,
                             const float* __restrict__ beta) {
    int c = threadIdx.x;
    float m = g_sum[c] * (1.f / NN);
    float v = g_sumsq[c] * (1.f / NN) - m * m;
    float rs = rsqrtf(v + BN_EPS);
    float sc = rs * gamma[c];
    g_scale[c] = sc;
    g_shift[c] = beta[c] - m * sc;
}

// ---------------- normalize ----------------
__global__ void normalize_kernel(int mode, int n4) {
    if (mode == 0 && blockIdx.x == 0 && threadIdx.x < HH) {
        g_sum[threadIdx.x] = 0.f;
        g_sumsq[threadIdx.x] = 0.f;
    }
    int i = blockIdx.x * blockDim.x + threadIdx.x;
    if (i >= n4) return;
    int c0 = (i * 4) & 127;
    float4 sc = *(const float4*)(g_scale + c0);
    float4 sh = *(const float4*)(g_shift + c0);
    float4 v = ((const float4*)g_u)[i];
    v.x = fmaxf(v.x * sc.x + sh.x, 0.f);
    v.y = fmaxf(v.y * sc.y + sh.y, 0.f);
    v.z = fmaxf(v.z * sc.z + sh.z, 0.f);
    v.w = fmaxf(v.w * sc.w + sh.w, 0.f);
    if (mode == 1) {
        v.x = 1.f / (1.f + expf(-v.x));
        v.y = 1.f / (1.f + expf(-v.y));
        v.z = 1.f / (1.f + expf(-v.z));
        v.w = 1.f / (1.f + expf(-v.w));
    }
    ((float4*)g_h)[i] = v;
    if (mode == 0) ((float4*)g_y)[i] = v;
}

// ---------------- per-graph mean pooling ----------------
__device__ __forceinline__ int lb_search(const void* bp, int target, bool i64) {
    int l = 0, r = NN;
    while (l < r) {
        int m = (l + r) >> 1;
        if (read_idx(bp, m, i64) < (long long)target) l = m + 1; else r = m;
    }
    return l;
}

__global__ void pool_kernel(const void* __restrict__ batchv) {
    const int g = blockIdx.x, c = threadIdx.x;
    const bool i64 = (g_idx64 != 0);
    int lo = lb_search(batchv, g, i64);
    int hi = lb_search(batchv, g + 1, i64);
    float s = 0.f;
    for (int i = lo; i < hi; i++) s += g_h[(size_t)i * HH + c];
    int cnt = hi - lo;
    g_pooled[g * HH + c] = s / fmaxf((float)cnt, 1.f);
}

// ---------------- fused action MLP ----------------
__device__ __forceinline__ void mlp_layer(float* z, const float* p_s,
                                          const float* __restrict__ Wrow,
                                          float bias, float gamma, float beta) {
#pragma unroll
    for (int r = 0; r < GG; r++) z[r] = bias;
    for (int k = 0; k < HH; k += 4) {
        float4 w = *(const float4*)(Wrow + k);
#pragma unroll
        for (int r = 0; r < GG; r++) {
            float4 p = *(const float4*)(p_s + r * HH + k);
            z[r] += w.x * p.x + w.y * p.y + w.z * p.z + w.w * p.w;
        }
    }
    float m = 0.f, s2 = 0.f;
#pragma unroll
    for (int r = 0; r < GG; r++) { m += z[r]; s2 += z[r] * z[r]; }
    m *= (1.f / GG);
    float v = s2 * (1.f / GG) - m * m;
    float sc = rsqrtf(v + BN_EPS) * gamma;
    float sh = beta - m * sc;
#pragma unroll
    for (int r = 0; r < GG; r++) z[r] = fmaxf(z[r] * sc + sh, 0.f);
}

__global__ void __launch_bounds__(128) mlp_kernel(
    const float* __restrict__ A1w, const float* __restrict__ A1b,
    const float* __restrict__ Ag1, const float* __restrict__ Ab1,
    const float* __restrict__ A2w, const float* __restrict__ A2b,
    const float* __restrict__ Ag2, const float* __restrict__ Ab2,
    const float* __restrict__ A3w, const float* __restrict__ A3b,
    float* __restrict__ out)
{
    __shared__ float p_s[GG * HH];
    const int c = threadIdx.x;
    for (int idx = c; idx < GG * HH; idx += 128) p_s[idx] = g_pooled[idx];
    __syncthreads();

    float z[GG];
    mlp_layer(z, p_s, A1w + c * HH, A1b[c], Ag1[c], Ab1[c]);
    __syncthreads();
#pragma unroll
    for (int r = 0; r < GG; r++) p_s[r * HH + c] = z[r];
    __syncthreads();

    mlp_layer(z, p_s, A2w + c * HH, A2b[c], Ag2[c], Ab2[c]);
    __syncthreads();
#pragma unroll
    for (int r = 0; r < GG; r++) p_s[r * HH + c] = z[r];
    __syncthreads();

    for (int idx = c; idx < GG * AA; idx += 128) {
        int r = idx >> 4, a2 = idx & 15;
        float acc = A3b[a2];
        for (int k = 0; k < HH; k++) acc += p_s[r * HH + k] * A3w[a2 * HH + k];
        out[idx] = 1.f / (1.f + expf(-acc));
    }
}

// ---------------- host launch ----------------
extern "C" void kernel_launch(void* const* d_in, const int* in_sizes, int n_in,
                              void* d_out, int out_size) {
    int ix, iea, iei, ib;
    int iW1, ib1, iWe1, ibe1, ig1, ibt1, iW2, ib2, iWe2, ibe2, ig2, ibt2;
    int iA1w, iA1b, iAg1, iAb1, iA2w, iA2b, iAg2, iAb2, iA3w, iA3b;
    if (in_sizes[2] == 2 * EE || in_sizes[2] == 4 * EE) {
        ix = 0; iea = 1; iei = 2; ib = 3;
        iW1 = 4; ib1 = 5; iWe1 = 6; ibe1 = 7; ig1 = 8; ibt1 = 9;
        iW2 = 10; ib2 = 11; iWe2 = 12; ibe2 = 13; ig2 = 14; ibt2 = 15;
        iA1w = 16; iA1b = 17; iAg1 = 18; iAb1 = 19;
        iA2w = 20; iA2b = 21; iAg2 = 22; iAb2 = 23; iA3w = 24; iA3b = 25;
    } else {
        ix = 0; iea = 1;
        iW1 = 2; ib1 = 3; iWe1 = 4; ibe1 = 5; ig1 = 6; ibt1 = 7;
        iW2 = 8; ib2 = 9; iWe2 = 10; ibe2 = 11; ig2 = 12; ibt2 = 13;
        iA1w = 14; iA1b = 15; iAg1 = 16; iAb1 = 17;
        iA2w = 18; iA2b = 19; iAg2 = 20; iAb2 = 21; iA3w = 22; iA3b = 23;
        iei = 24; ib = 25;
    }

    const float* x   = (const float*)d_in[ix];
    const float* ea  = (const float*)d_in[iea];
    const void*  ei  = d_in[iei];
    const void*  bat = d_in[ib];
    float* out = (float*)d_out;

    const int n4 = NN * HH / 4;
    const int copy_blocks = (n4 + 255) / 256;
    const int edge_blocks = (NTILES + 63) / 64;      // 782
    const int gemm_blocks = (NN + 127) / 128;        // 391
    const int red_blocks  = (NN + 255) / 256;
    const int e_blocks    = (EE + 255) / 256;        // 3125

    detect_kernel<<<1, 256>>>((const unsigned int*)ei);

    // ---- counting sort by dst (shared by both layers) ----
    zero_cnt_kernel<<<NB, 256>>>();
    hist_kernel<<<e_blocks, 256>>>(ei);
    bsum_kernel<<<NB, 256>>>();
    scan_bsum_kernel<<<1, 256>>>();
    offs_kernel<<<NB, 256>>>();
    scatter_kernel<<<e_blocks, 256>>>(ei);

    // ---- layer 1 ----
    copy_init_kernel<<<copy_blocks, 256>>>((const float4*)x, n4);
    edge_sorted_kernel<<<edge_blocks, 256>>>(x, 0, ea,
                                             (const float*)d_in[iWe1], (const float*)d_in[ibe1]);
    node_gemm_mma_kernel<<<gemm_blocks, 512>>>((const float*)d_in[iW1], (const float*)d_in[ib1]);
    colreduce_kernel<<<red_blocks, 128>>>();
    stats_kernel<<<1, 128>>>((const float*)d_in[ig1], (const float*)d_in[ibt1]);
    normalize_kernel<<<copy_blocks, 256>>>(0, n4);

    // ---- layer 2 ----
    edge_sorted_kernel<<<edge_blocks, 256>>>(x, 1, ea,
                                             (const float*)d_in[iWe2], (const float*)d_in[ibe2]);
    node_gemm_mma_kernel<<<gemm_blocks, 512>>>((const float*)d_in[iW2], (const float*)d_in[ib2]);
    colreduce_kernel<<<red_blocks, 128>>>();
    stats_kernel<<<1, 128>>>((const float*)d_in[ig2], (const float*)d_in[ibt2]);
    normalize_kernel<<<copy_blocks, 256>>>(1, n4);

    // ---- pool + MLP ----
    pool_kernel<<<GG, 128>>>(bat);
    mlp_kernel<<<1, 128>>>((const float*)d_in[iA1w], (const float*)d_in[iA1b],
                           (const float*)d_in[iAg1], (const float*)d_in[iAb1],
                           (const float*)d_in[iA2w], (const float*)d_in[iA2b],
                           (const float*)d_in[iAg2], (const float*)d_in[iAb2],
                           (const float*)d_in[iA3w], (const float*)d_in[iA3b], out);
}

// round 4
// speedup vs baseline: 1.1333x; 1.1333x over previous
#include <cuda_runtime.h>
#include <cuda_bf16.h>
#include <math.h>

#define NN 50000
#define EE 800000
#define HH 128
#define EDIM 32
#define GG 64
#define AA 16
#define BN_EPS 1e-5f
#define FULLM 0xffffffffu

// ---------------- scratch (static device globals; no allocation) ----------------
__device__ float g_y[(size_t)NN * HH];
__device__ float g_u[(size_t)NN * HH];
__device__ float g_h[(size_t)NN * HH];
__device__ float g_sum[HH];
__device__ float g_sumsq[HH];
__device__ float g_scale[HH];
__device__ float g_shift[HH];
__device__ float g_pooled[GG * HH];
__device__ int   g_idx64;

// ---------------- int32/int64 index handling ----------------
__device__ __forceinline__ long long read_idx(const void* p, long long i, bool i64) {
    if (i64) return ((const long long*)p)[i];
    return (long long)((const int*)p)[i];
}

__global__ void detect_kernel(const unsigned int* __restrict__ w) {
    __shared__ int f;
    if (threadIdx.x == 0) f = 0;
    __syncthreads();
    int local = 0;
    for (int i = threadIdx.x * 2 + 1; i < 8192; i += 512)
        if (w[i]) local = 1;
    if (local) atomicOr(&f, 1);
    __syncthreads();
    if (threadIdx.x == 0) g_idx64 = f ? 0 : 1;
}

// ---------------- bf16 2-split helpers ----------------
// pack2(e0,e1): .b32 with e0 in low half (lower k), e1 in high half.
__device__ __forceinline__ unsigned pack2(float e0, float e1) {
    unsigned r;
    asm("cvt.rn.bf16x2.f32 %0, %1, %2;" : "=r"(r) : "f"(e1), "f"(e0));
    return r;
}
// hi = bf16(x); lo = bf16(x - hi). bf16->f32 is a 16-bit shift.
__device__ __forceinline__ void split2(float e0, float e1, unsigned& hi, unsigned& lo) {
    hi = pack2(e0, e1);
    float f0 = __uint_as_float(hi << 16);
    float f1 = __uint_as_float(hi & 0xffff0000u);
    lo = pack2(e0 - f0, e1 - f1);
}
__device__ __forceinline__ void mma_bf16(float& c0, float& c1, float& c2, float& c3,
                                         unsigned a0, unsigned a1, unsigned a2, unsigned a3,
                                         unsigned b0, unsigned b1) {
    asm volatile("mma.sync.aligned.m16n8k16.row.col.f32.bf16.bf16.f32 "
                 "{%0,%1,%2,%3}, {%4,%5,%6,%7}, {%8,%9}, {%0,%1,%2,%3};"
                 : "+f"(c0), "+f"(c1), "+f"(c2), "+f"(c3)
                 : "r"(a0), "r"(a1), "r"(a2), "r"(a3), "r"(b0), "r"(b1));
}

// Stage pre-split B fragments for one k32 block.
// bfrag[(nt*2+kc)*32 + lane] = (bh0, bh1, bl0, bl1) for col c = nt*8+g, k-pairs
// (k0, k0+1) and (k0+8, k0+9) with k0 = kbase + 16*kc + 2*t.
__device__ __forceinline__ void stage_bfrag(float4* bfrag, const float* __restrict__ Wmat,
                                            int ldw, int kbase, int tid, int nthreads) {
    for (int idx = tid; idx < 1024; idx += nthreads) {
        int nt = idx >> 6, kc = (idx >> 5) & 1, ln = idx & 31;
        int g2 = ln >> 2, t2 = ln & 3;
        int c = nt * 8 + g2;
        int k0 = kbase + 16 * kc + 2 * t2;
        float w00 = Wmat[c * ldw + k0];
        float w01 = Wmat[c * ldw + k0 + 1];
        float w10 = Wmat[c * ldw + k0 + 8];
        float w11 = Wmat[c * ldw + k0 + 9];
        unsigned bh0, bl0, bh1, bl1;
        split2(w00, w01, bh0, bl0);
        split2(w10, w11, bh1, bl1);
        bfrag[idx] = make_float4(__uint_as_float(bh0), __uint_as_float(bh1),
                                 __uint_as_float(bl0), __uint_as_float(bl1));
    }
}

// Load + split A fragments (rows r0,r1; one k32 block at kbase) for thread (t).
// Produces ahi[kc][4], alo[kc][4] for kc=0,1.
__device__ __forceinline__ void load_split_a(const float* __restrict__ row0,
                                             const float* __restrict__ row1,
                                             int kbase, int t,
                                             unsigned ahi[2][4], unsigned alo[2][4]) {
#pragma unroll
    for (int kc = 0; kc < 2; kc++) {
        int k0 = kbase + 16 * kc + 2 * t;
        float2 p00 = *(const float2*)(row0 + k0);
        float2 p01 = *(const float2*)(row0 + k0 + 8);
        float2 p10 = *(const float2*)(row1 + k0);
        float2 p11 = *(const float2*)(row1 + k0 + 8);
        split2(p00.x, p00.y, ahi[kc][0], alo[kc][0]);
        split2(p10.x, p10.y, ahi[kc][1], alo[kc][1]);
        split2(p01.x, p01.y, ahi[kc][2], alo[kc][2]);
        split2(p11.x, p11.y, ahi[kc][3], alo[kc][3]);
    }
}

// ---------------- y = src (copy), zero BN stats ----------------
__global__ void copy_init_kernel(const float4* __restrict__ src, int n4) {
    if (blockIdx.x == 0 && threadIdx.x < HH) {
        g_sum[threadIdx.x] = 0.f;
        g_sumsq[threadIdx.x] = 0.f;
    }
    int i = blockIdx.x * blockDim.x + threadIdx.x;
    if (i < n4) ((float4*)g_y)[i] = src[i];
}

// ---------------- edge kernel (bf16 2-split mma elin) ----------------
#define NTILES 50000         // EE/16
#define WTILES 8
__global__ void __launch_bounds__(256) edge_mma_kernel(
    const float* __restrict__ xin_ext, int use_h,
    const float* __restrict__ ea,
    const void* __restrict__ eiv,
    const float* __restrict__ We,   // [128][32] row-major
    const float* __restrict__ be)
{
    __shared__ float4 bfrag[16 * 2 * 32];   // 16KB
    __shared__ float be_s[HH];

    const int tid = threadIdx.x;
    stage_bfrag(bfrag, We, EDIM, 0, tid, 256);
    if (tid < HH) be_s[tid] = be[tid];
    __syncthreads();

    const float* __restrict__ xin = use_h ? g_h : xin_ext;
    const int lane = tid & 31, warp = tid >> 5;
    const int g = lane >> 2, t = lane & 3;
    const bool i64 = (g_idx64 != 0);
    const bool even = ((t & 1) == 0);
    const int erow = even ? g : g + 8;
    const int cboff = (t & 2) ? 4 : 0;

    for (int it = 0; it < WTILES; it++) {
        int tile = (blockIdx.x * 8 + warp) * WTILES + it;
        if (tile >= NTILES) break;
        long long e0 = (long long)tile * 16;

        int sv = 0, dv = 0;
        if (lane < 16) {
            sv = (int)read_idx(eiv, e0 + lane, i64);
            dv = (int)read_idx(eiv, (long long)EE + e0 + lane, i64);
        }
        int my_s = __shfl_sync(FULLM, sv, erow);
        int my_d = __shfl_sync(FULLM, dv, erow);
        const float* srcp = xin + (size_t)my_s * HH + cboff;
        float*       dstp = g_y + (size_t)my_d * HH + cboff;

        const float* row0 = ea + (size_t)(e0 + g) * EDIM;
        const float* row1 = ea + (size_t)(e0 + g + 8) * EDIM;
        unsigned ahi[2][4], alo[2][4];
        load_split_a(row0, row1, 0, t, ahi, alo);

#pragma unroll 4
        for (int nt = 0; nt < 16; nt++) {
            float2 b2 = *(const float2*)(be_s + nt * 8 + 2 * t);
            float c0 = b2.x, c1 = b2.y, c2 = b2.x, c3 = b2.y;
#pragma unroll
            for (int kc = 0; kc < 2; kc++) {
                float4 bf = bfrag[(nt * 2 + kc) * 32 + lane];
                unsigned bh0 = __float_as_uint(bf.x), bh1 = __float_as_uint(bf.y);
                unsigned bl0 = __float_as_uint(bf.z), bl1 = __float_as_uint(bf.w);
                mma_bf16(c0, c1, c2, c3, ahi[kc][0], ahi[kc][1], ahi[kc][2], ahi[kc][3], bh0, bh1);
                mma_bf16(c0, c1, c2, c3, alo[kc][0], alo[kc][1], alo[kc][2], alo[kc][3], bh0, bh1);
                mma_bf16(c0, c1, c2, c3, ahi[kc][0], ahi[kc][1], ahi[kc][2], ahi[kc][3], bl0, bl1);
            }
            // pair exchange -> float4 of one edge
            float s0 = even ? c2 : c0;
            float s1 = even ? c3 : c1;
            float r0 = __shfl_xor_sync(FULLM, s0, 1);
            float r1 = __shfl_xor_sync(FULLM, s1, 1);
            float o0, o1, o2, o3;
            if (even) { o0 = c0; o1 = c1; o2 = r0; o3 = r1; }
            else      { o0 = r0; o1 = r1; o2 = c2; o3 = c3; }

            float4 xv = *(const float4*)(srcp + nt * 8);
            o0 = fmaxf(o0 + xv.x, 0.f);
            o1 = fmaxf(o1 + xv.y, 0.f);
            o2 = fmaxf(o2 + xv.z, 0.f);
            o3 = fmaxf(o3 + xv.w, 0.f);
            asm volatile("red.global.add.v4.f32 [%0], {%1,%2,%3,%4};"
                         :: "l"(dstp + nt * 8), "f"(o0), "f"(o1), "f"(o2), "f"(o3) : "memory");
        }
    }
}

// ---------------- node GEMM (bf16 2-split): u = g_y @ W.T + b ----------------
// 512 threads, 16 warps. Warp: 16 rows x 64 cols. Block: 128 rows x 128 cols.
__global__ void __launch_bounds__(512) node_gemm_mma_kernel(
    const float* __restrict__ W,
    const float* __restrict__ b)
{
    __shared__ float4 bfrag[16 * 2 * 32];   // restaged per k32 block, 16KB
    __shared__ float b_s[HH];

    const int tid = threadIdx.x;
    const int lane = tid & 31, warp = tid >> 5;
    const int g = lane >> 2, t = lane & 3;
    const int colhalf = warp >> 3;
    const int rw = warp & 7;
    const int nt0 = colhalf * 8;
    const int rowbase = blockIdx.x * 128 + rw * 16;
    const bool active = (rowbase < NN);      // NN % 16 == 0
    const bool even = ((t & 1) == 0);
    const int cboff = (t & 2) ? 4 : 0;

    if (tid < HH) b_s[tid] = b[tid];

    float C[8][4];
#pragma unroll
    for (int nt = 0; nt < 8; nt++)
#pragma unroll
        for (int q = 0; q < 4; q++) C[nt][q] = 0.f;

    for (int kb = 0; kb < 4; kb++) {
        __syncthreads();
        stage_bfrag(bfrag, W, HH, kb * 32, tid, 512);
        __syncthreads();

        if (active) {
            const float* row0 = g_y + (size_t)(rowbase + g) * HH;
            const float* row1 = g_y + (size_t)(rowbase + g + 8) * HH;
            unsigned ahi[2][4], alo[2][4];
            load_split_a(row0, row1, kb * 32, t, ahi, alo);

#pragma unroll
            for (int ntl = 0; ntl < 8; ntl++) {
                int nt = nt0 + ntl;
#pragma unroll
                for (int kc = 0; kc < 2; kc++) {
                    float4 bf = bfrag[(nt * 2 + kc) * 32 + lane];
                    unsigned bh0 = __float_as_uint(bf.x), bh1 = __float_as_uint(bf.y);
                    unsigned bl0 = __float_as_uint(bf.z), bl1 = __float_as_uint(bf.w);
                    mma_bf16(C[ntl][0], C[ntl][1], C[ntl][2], C[ntl][3],
                             ahi[kc][0], ahi[kc][1], ahi[kc][2], ahi[kc][3], bh0, bh1);
                    mma_bf16(C[ntl][0], C[ntl][1], C[ntl][2], C[ntl][3],
                             alo[kc][0], alo[kc][1], alo[kc][2], alo[kc][3], bh0, bh1);
                    mma_bf16(C[ntl][0], C[ntl][1], C[ntl][2], C[ntl][3],
                             ahi[kc][0], ahi[kc][1], ahi[kc][2], ahi[kc][3], bl0, bl1);
                }
            }
        }
    }

    if (active) {
        const int orow = rowbase + (even ? g : g + 8);
        float* outp = g_u + (size_t)orow * HH + cboff;
#pragma unroll
        for (int ntl = 0; ntl < 8; ntl++) {
            int nt = nt0 + ntl;
            float c0 = C[ntl][0] + b_s[nt * 8 + 2 * t];
            float c1 = C[ntl][1] + b_s[nt * 8 + 2 * t + 1];
            float c2 = C[ntl][2] + b_s[nt * 8 + 2 * t];
            float c3 = C[ntl][3] + b_s[nt * 8 + 2 * t + 1];
            float s0 = even ? c2 : c0;
            float s1 = even ? c3 : c1;
            float r0 = __shfl_xor_sync(FULLM, s0, 1);
            float r1 = __shfl_xor_sync(FULLM, s1, 1);
            float4 o;
            if (even) { o = make_float4(c0, c1, r0, r1); }
            else      { o = make_float4(r0, r1, c2, c3); }
            *(float4*)(outp + nt * 8) = o;
        }
    }
}

// ---------------- per-channel BN stats ----------------
__global__ void colreduce_kernel() {
    const int c = threadIdx.x;
    const int r0 = blockIdx.x * 256;
    const int r1 = min(r0 + 256, NN);
    float s = 0.f, s2 = 0.f;
    for (int r = r0; r < r1; r++) {
        float v = g_u[(size_t)r * HH + c];
        s += v; s2 += v * v;
    }
    atomicAdd(&g_sum[c], s);
    atomicAdd(&g_sumsq[c], s2);
}

__global__ void stats_kernel(const float* __restrict__ gamma,
                             const float* __restrict__ beta) {
    int c = threadIdx.x;
    float m = g_sum[c] * (1.f / NN);
    float v = g_sumsq[c] * (1.f / NN) - m * m;
    float rs = rsqrtf(v + BN_EPS);
    float sc = rs * gamma[c];
    g_scale[c] = sc;
    g_shift[c] = beta[c] - m * sc;
}

// ---------------- normalize ----------------
__global__ void normalize_kernel(int mode, int n4) {
    if (mode == 0 && blockIdx.x == 0 && threadIdx.x < HH) {
        g_sum[threadIdx.x] = 0.f;
        g_sumsq[threadIdx.x] = 0.f;
    }
    int i = blockIdx.x * blockDim.x + threadIdx.x;
    if (i >= n4) return;
    int c0 = (i * 4) & 127;
    float4 sc = *(const float4*)(g_scale + c0);
    float4 sh = *(const float4*)(g_shift + c0);
    float4 v = ((const float4*)g_u)[i];
    v.x = fmaxf(v.x * sc.x + sh.x, 0.f);
    v.y = fmaxf(v.y * sc.y + sh.y, 0.f);
    v.z = fmaxf(v.z * sc.z + sh.z, 0.f);
    v.w = fmaxf(v.w * sc.w + sh.w, 0.f);
    if (mode == 1) {
        v.x = 1.f / (1.f + expf(-v.x));
        v.y = 1.f / (1.f + expf(-v.y));
        v.z = 1.f / (1.f + expf(-v.z));
        v.w = 1.f / (1.f + expf(-v.w));
    }
    ((float4*)g_h)[i] = v;
    if (mode == 0) ((float4*)g_y)[i] = v;
}

// ---------------- per-graph mean pooling ----------------
__device__ __forceinline__ int lb_search(const void* bp, int target, bool i64) {
    int l = 0, r = NN;
    while (l < r) {
        int m = (l + r) >> 1;
        if (read_idx(bp, m, i64) < (long long)target) l = m + 1; else r = m;
    }
    return l;
}

__global__ void pool_kernel(const void* __restrict__ batchv) {
    const int g = blockIdx.x, c = threadIdx.x;
    const bool i64 = (g_idx64 != 0);
    int lo = lb_search(batchv, g, i64);
    int hi = lb_search(batchv, g + 1, i64);
    float s = 0.f;
    for (int i = lo; i < hi; i++) s += g_h[(size_t)i * HH + c];
    int cnt = hi - lo;
    g_pooled[g * HH + c] = s / fmaxf((float)cnt, 1.f);
}

// ---------------- fused action MLP ----------------
__device__ __forceinline__ void mlp_layer(float* z, const float* p_s,
                                          const float* __restrict__ Wrow,
                                          float bias, float gamma, float beta) {
#pragma unroll
    for (int r = 0; r < GG; r++) z[r] = bias;
    for (int k = 0; k < HH; k += 4) {
        float4 w = *(const float4*)(Wrow + k);
#pragma unroll
        for (int r = 0; r < GG; r++) {
            float4 p = *(const float4*)(p_s + r * HH + k);
            z[r] += w.x * p.x + w.y * p.y + w.z * p.z + w.w * p.w;
        }
    }
    float m = 0.f, s2 = 0.f;
#pragma unroll
    for (int r = 0; r < GG; r++) { m += z[r]; s2 += z[r] * z[r]; }
    m *= (1.f / GG);
    float v = s2 * (1.f / GG) - m * m;
    float sc = rsqrtf(v + BN_EPS) * gamma;
    float sh = beta - m * sc;
#pragma unroll
    for (int r = 0; r < GG; r++) z[r] = fmaxf(z[r] * sc + sh, 0.f);
}

__global__ void __launch_bounds__(128) mlp_kernel(
    const float* __restrict__ A1w, const float* __restrict__ A1b,
    const float* __restrict__ Ag1, const float* __restrict__ Ab1,
    const float* __restrict__ A2w, const float* __restrict__ A2b,
    const float* __restrict__ Ag2, const float* __restrict__ Ab2,
    const float* __restrict__ A3w, const float* __restrict__ A3b,
    float* __restrict__ out)
{
    __shared__ float p_s[GG * HH];
    const int c = threadIdx.x;
    for (int idx = c; idx < GG * HH; idx += 128) p_s[idx] = g_pooled[idx];
    __syncthreads();

    float z[GG];
    mlp_layer(z, p_s, A1w + c * HH, A1b[c], Ag1[c], Ab1[c]);
    __syncthreads();
#pragma unroll
    for (int r = 0; r < GG; r++) p_s[r * HH + c] = z[r];
    __syncthreads();

    mlp_layer(z, p_s, A2w + c * HH, A2b[c], Ag2[c], Ab2[c]);
    __syncthreads();
#pragma unroll
    for (int r = 0; r < GG; r++) p_s[r * HH + c] = z[r];
    __syncthreads();

    for (int idx = c; idx < GG * AA; idx += 128) {
        int r = idx >> 4, a2 = idx & 15;
        float acc = A3b[a2];
        for (int k = 0; k < HH; k++) acc += p_s[r * HH + k] * A3w[a2 * HH + k];
        out[idx] = 1.f / (1.f + expf(-acc));
    }
}

// ---------------- host launch ----------------
extern "C" void kernel_launch(void* const* d_in, const int* in_sizes, int n_in,
                              void* d_out, int out_size) {
    int ix, iea, iei, ib;
    int iW1, ib1, iWe1, ibe1, ig1, ibt1, iW2, ib2, iWe2, ibe2, ig2, ibt2;
    int iA1w, iA1b, iAg1, iAb1, iA2w, iA2b, iAg2, iAb2, iA3w, iA3b;
    if (in_sizes[2] == 2 * EE || in_sizes[2] == 4 * EE) {
        ix = 0; iea = 1; iei = 2; ib = 3;
        iW1 = 4; ib1 = 5; iWe1 = 6; ibe1 = 7; ig1 = 8; ibt1 = 9;
        iW2 = 10; ib2 = 11; iWe2 = 12; ibe2 = 13; ig2 = 14; ibt2 = 15;
        iA1w = 16; iA1b = 17; iAg1 = 18; iAb1 = 19;
        iA2w = 20; iA2b = 21; iAg2 = 22; iAb2 = 23; iA3w = 24; iA3b = 25;
    } else {
        ix = 0; iea = 1;
        iW1 = 2; ib1 = 3; iWe1 = 4; ibe1 = 5; ig1 = 6; ibt1 = 7;
        iW2 = 8; ib2 = 9; iWe2 = 10; ibe2 = 11; ig2 = 12; ibt2 = 13;
        iA1w = 14; iA1b = 15; iAg1 = 16; iAb1 = 17;
        iA2w = 18; iA2b = 19; iAg2 = 20; iAb2 = 21; iA3w = 22; iA3b = 23;
        iei = 24; ib = 25;
    }

    const float* x   = (const float*)d_in[ix];
    const float* ea  = (const float*)d_in[iea];
    const void*  ei  = d_in[iei];
    const void*  bat = d_in[ib];
    float* out = (float*)d_out;

    const int n4 = NN * HH / 4;
    const int copy_blocks = (n4 + 255) / 256;
    const int edge_blocks = (NTILES + 63) / 64;      // 782
    const int gemm_blocks = (NN + 127) / 128;        // 391
    const int red_blocks  = (NN + 255) / 256;

    detect_kernel<<<1, 256>>>((const unsigned int*)ei);

    // ---- layer 1 ----
    copy_init_kernel<<<copy_blocks, 256>>>((const float4*)x, n4);
    edge_mma_kernel<<<edge_blocks, 256>>>(x, 0, ea, ei,
                                          (const float*)d_in[iWe1], (const float*)d_in[ibe1]);
    node_gemm_mma_kernel<<<gemm_blocks, 512>>>((const float*)d_in[iW1], (const float*)d_in[ib1]);
    colreduce_kernel<<<red_blocks, 128>>>();
    stats_kernel<<<1, 128>>>((const float*)d_in[ig1], (const float*)d_in[ibt1]);
    normalize_kernel<<<copy_blocks, 256>>>(0, n4);

    // ---- layer 2 ----
    edge_mma_kernel<<<edge_blocks, 256>>>(x, 1, ea, ei,
                                          (const float*)d_in[iWe2], (const float*)d_in[ibe2]);
    node_gemm_mma_kernel<<<gemm_blocks, 512>>>((const float*)d_in[iW2], (const float*)d_in[ib2]);
    colreduce_kernel<<<red_blocks, 128>>>();
    stats_kernel<<<1, 128>>>((const float*)d_in[ig2], (const float*)d_in[ibt2]);
    normalize_kernel<<<copy_blocks, 256>>>(1, n4);

    // ---- pool + MLP ----
    pool_kernel<<<GG, 128>>>(bat);
    mlp_kernel<<<1, 128>>>((const float*)d_in[iA1w], (const float*)d_in[iA1b],
                           (const float*)d_in[iAg1], (const float*)d_in[iAb1],
                           (const float*)d_in[iA2w], (const float*)d_in[iA2b],
                           (const float*)d_in[iAg2], (const float*)d_in[iAb2],
                           (const float*)d_in[iA3w], (const float*)d_in[iA3b], out);
}